// round 14
// baseline (speedup 1.0000x reference)
#include <cuda_runtime.h>
#include <math.h>
#include <stdint.h>

#define BATCH   2
#define T_SEQ   2048
#define CDIM    1024
#define HEADS   16
#define DHEAD   64
#define C3      3072
#define MROWS   4096

__device__ float g_qkv[(size_t)MROWS * C3];   // 48 MB
__device__ float g_y  [(size_t)MROWS * CDIM]; // 16 MB

// ---- tf32 helpers ----------------------------------------------------------
__device__ __forceinline__ uint32_t f2tf32(float x) {
    uint32_t u; asm("cvt.rna.tf32.f32 %0, %1;" : "=r"(u) : "f"(x)); return u;
}
__device__ __forceinline__ void mma_tf32(float* d, const uint32_t* a, const uint32_t* b) {
    asm volatile("mma.sync.aligned.m16n8k8.row.col.f32.tf32.tf32.f32 "
        "{%0,%1,%2,%3}, {%4,%5,%6,%7}, {%8,%9}, {%0,%1,%2,%3};"
        : "+f"(d[0]), "+f"(d[1]), "+f"(d[2]), "+f"(d[3])
        : "r"(a[0]), "r"(a[1]), "r"(a[2]), "r"(a[3]), "r"(b[0]), "r"(b[1]));
}
// split float4 -> tf32 hi/lo float4s
__device__ __forceinline__ void split4(float4 v, float4& h, float4& l) {
    uint32_t hx = f2tf32(v.x), hy = f2tf32(v.y), hz = f2tf32(v.z), hw = f2tf32(v.w);
    h = make_float4(__uint_as_float(hx), __uint_as_float(hy),
                    __uint_as_float(hz), __uint_as_float(hw));
    l = make_float4(__uint_as_float(f2tf32(v.x - __uint_as_float(hx))),
                    __uint_as_float(f2tf32(v.y - __uint_as_float(hy))),
                    __uint_as_float(f2tf32(v.z - __uint_as_float(hz))),
                    __uint_as_float(f2tf32(v.w - __uint_as_float(hw))));
}

// ---------------------------------------------------------------------------
// NT GEMM on tensor cores (exact R11 version, measured 438us).
// ---------------------------------------------------------------------------
#define GS_PANEL 520
#define GS_A_HI  0
#define GS_A_LO  (4 * GS_PANEL)
#define GS_B_HI  (8 * GS_PANEL)
#define GS_B_LO  (12 * GS_PANEL)
#define GS_BUF   (16 * GS_PANEL)

__global__ void __launch_bounds__(256, 2)
gemm_tf32_kernel(const float* __restrict__ A,
                 const float* __restrict__ B,
                 float* __restrict__ C,
                 int M, int N, int K)
{
    extern __shared__ __align__(16) float gsm[];

    const int t    = threadIdx.x;
    const int lane = t & 31;
    const int w    = t >> 5;
    const int wm   = w >> 2;
    const int wn   = w & 3;
    const int grp  = lane >> 2;
    const int qt   = lane & 3;
    const int m0   = blockIdx.y * 128;
    const int n0   = blockIdx.x * 128;

    const int srow = t >> 2;
    const int sc4  = t & 3;

    float acc[4][4][4];
    #pragma unroll
    for (int mt = 0; mt < 4; mt++)
        #pragma unroll
        for (int nt = 0; nt < 4; nt++)
            #pragma unroll
            for (int i = 0; i < 4; i++) acc[mt][nt][i] = 0.f;

    const float* Ap0 = A + (size_t)(m0 + srow)      * K + sc4 * 4;
    const float* Ap1 = A + (size_t)(m0 + srow + 64) * K + sc4 * 4;
    const float* Bp0 = B + (size_t)(n0 + srow)      * K + sc4 * 4;
    const float* Bp1 = B + (size_t)(n0 + srow + 64) * K + sc4 * 4;

    auto stage = [&](float4 va0, float4 va1, float4 vb0, float4 vb1, int buf) {
        float* bb = gsm + buf * GS_BUF;
        const int off0 = sc4 * GS_PANEL + srow * 4;
        const int off1 = off0 + 256;
        float4 h, l;
        split4(va0, h, l); *(float4*)&bb[GS_A_HI + off0] = h; *(float4*)&bb[GS_A_LO + off0] = l;
        split4(va1, h, l); *(float4*)&bb[GS_A_HI + off1] = h; *(float4*)&bb[GS_A_LO + off1] = l;
        split4(vb0, h, l); *(float4*)&bb[GS_B_HI + off0] = h; *(float4*)&bb[GS_B_LO + off0] = l;
        split4(vb1, h, l); *(float4*)&bb[GS_B_HI + off1] = h; *(float4*)&bb[GS_B_LO + off1] = l;
    };

    float4 va0 = *(const float4*)Ap0, va1 = *(const float4*)Ap1;
    float4 vb0 = *(const float4*)Bp0, vb1 = *(const float4*)Bp1;
    stage(va0, va1, vb0, vb1, 0);
    __syncthreads();

    const int abase = (wm * 64 + grp) * 4 + qt;
    const int bbase = (wn * 32 + grp) * 4 + qt;

    const int nch = K / 16;
    for (int ch = 0; ch < nch; ch++) {
        const bool has = (ch + 1 < nch);
        if (has) {
            va0 = *(const float4*)(Ap0 + (ch + 1) * 16);
            va1 = *(const float4*)(Ap1 + (ch + 1) * 16);
            vb0 = *(const float4*)(Bp0 + (ch + 1) * 16);
            vb1 = *(const float4*)(Bp1 + (ch + 1) * 16);
        }

        const float* Sb = gsm + (ch & 1) * GS_BUF;
        #pragma unroll
        for (int kg = 0; kg < 2; kg++) {
            const int pk = kg * 2 * GS_PANEL;
            uint32_t bh[4][2], bl[4][2];
            #pragma unroll
            for (int nt = 0; nt < 4; nt++) {
                const int o = pk + bbase + nt * 32;
                bh[nt][0] = __float_as_uint(Sb[GS_B_HI + o]);
                bh[nt][1] = __float_as_uint(Sb[GS_B_HI + o + GS_PANEL]);
                bl[nt][0] = __float_as_uint(Sb[GS_B_LO + o]);
                bl[nt][1] = __float_as_uint(Sb[GS_B_LO + o + GS_PANEL]);
            }
            #pragma unroll
            for (int mt = 0; mt < 4; mt++) {
                const int o = pk + abase + mt * 64;
                uint32_t ah[4], al[4];
                ah[0] = __float_as_uint(Sb[GS_A_HI + o]);
                ah[1] = __float_as_uint(Sb[GS_A_HI + o + 32]);
                ah[2] = __float_as_uint(Sb[GS_A_HI + o + GS_PANEL]);
                ah[3] = __float_as_uint(Sb[GS_A_HI + o + GS_PANEL + 32]);
                al[0] = __float_as_uint(Sb[GS_A_LO + o]);
                al[1] = __float_as_uint(Sb[GS_A_LO + o + 32]);
                al[2] = __float_as_uint(Sb[GS_A_LO + o + GS_PANEL]);
                al[3] = __float_as_uint(Sb[GS_A_LO + o + GS_PANEL + 32]);
                #pragma unroll
                for (int nt = 0; nt < 4; nt++) {
                    mma_tf32(acc[mt][nt], ah, bh[nt]);
                    mma_tf32(acc[mt][nt], al, bh[nt]);
                    mma_tf32(acc[mt][nt], ah, bl[nt]);
                }
            }
        }
        __syncthreads();
        if (has) {
            stage(va0, va1, vb0, vb1, (ch + 1) & 1);
            __syncthreads();
        }
    }

    #pragma unroll
    for (int mt = 0; mt < 4; mt++) {
        #pragma unroll
        for (int nt = 0; nt < 4; nt++) {
            const int row = m0 + wm * 64 + mt * 16 + grp;
            const int col = n0 + wn * 32 + nt * 8 + qt * 2;
            *(float2*)&C[(size_t)row * N + col]       = make_float2(acc[mt][nt][0], acc[mt][nt][1]);
            *(float2*)&C[(size_t)(row + 8) * N + col] = make_float2(acc[mt][nt][2], acc[mt][nt][3]);
        }
    }
}

// ---------------------------------------------------------------------------
// Penalized attention with TENSOR-CORE QK.
// softmax(P - Z) == softmax(P[k] + prefix_excl_sigmoid(k)).
// Per 64q x 64k tile: P = Q@K^T via 3xTF32 mma (Q panels staged once/block,
// K panels per tile) -> P to SMEM -> sigmoid pair-scan + shifted exp (scalar)
// -> AV scalar. 120.8 KB smem, 1 CTA/SM.
// Panel layout (64 rows): addr(row,k) = (k/4)*268 + row*4 + k%4 (conflict-free
// STS.128 staging and LDS.32 frag loads, proven pattern from the GEMM).
// ---------------------------------------------------------------------------
#define AT_PANEL 268
#define AT_QH    0
#define AT_QL    (16 * AT_PANEL)          // 4288
#define AT_KH    (32 * AT_PANEL)          // 8576
#define AT_KL    (48 * AT_PANEL)          // 12864
#define AT_V     (64 * AT_PANEL)          // 17152  (64 x 68)
#define AT_P     (AT_V + 64 * 68)         // 21504  (64 x 72)
#define AT_E     (AT_P + 64 * 72)         // 26112  (64 x 64)
#define AT_TOTAL (AT_E + 64 * 64)         // 30208 floats = 120832 B

__global__ void __launch_bounds__(256)
attn_kernel(const float* __restrict__ qkv, float* __restrict__ yout)
{
    extern __shared__ __align__(16) float sm[];
    float* Qh  = sm + AT_QH;
    float* Ql  = sm + AT_QL;
    float* Kh  = sm + AT_KH;
    float* Kl  = sm + AT_KL;
    float* Vsh = sm + AT_V;
    float* Psh = sm + AT_P;
    float* esh = sm + AT_E;

    const int b     = blockIdx.z;
    const int h     = blockIdx.y;
    const int qbase = (int)(gridDim.x - 1 - blockIdx.x) * 64;  // longest first
    const int w     = threadIdx.x >> 5;
    const int lane  = threadIdx.x & 31;
    const int grp   = lane >> 2;
    const int qt    = lane & 3;
    const int d0    = 2 * lane;
    const float scale = 0.125f;

    // ---- stage Q panels hi/lo (once per block) ----
    #pragma unroll
    for (int i = 0; i < 4; i++) {
        int idx = threadIdx.x + i * 256;
        int r = idx >> 4, c4 = idx & 15;
        const float* qptr = qkv + (size_t)(b * T_SEQ + qbase + r) * C3 + h * DHEAD + c4 * 4;
        float4 v = *(const float4*)qptr;
        float4 hi, lo; split4(v, hi, lo);
        int o = c4 * AT_PANEL + r * 4;
        *(float4*)&Qh[o] = hi;
        *(float4*)&Ql[o] = lo;
    }

    const float* Kbase = qkv + (size_t)(b * T_SEQ) * C3 + CDIM     + h * DHEAD;
    const float* Vbase = qkv + (size_t)(b * T_SEQ) * C3 + 2 * CDIM + h * DHEAD;
    const int ntiles = (qbase >> 6) + 1;

    float denl[8], y0[8], y1[8];
    #pragma unroll
    for (int g = 0; g < 8; g++) { denl[g] = 0.f; y0[g] = 0.f; y1[g] = 0.f; }

    const int mbase = (w & 3) * 16;     // mma query-row tile
    const int nbase = (w >> 2) * 32;    // mma key-col tile

    for (int tile = 0; tile < ntiles; tile++) {
        const int kt0 = tile << 6;
        __syncthreads();   // prev consumers done (also covers Q staging, tile 0)

        // ---- stage K panels hi/lo + V plain ----
        #pragma unroll
        for (int i = 0; i < 4; i++) {
            int idx = threadIdx.x + i * 256;
            int r = idx >> 4, c4 = idx & 15;
            size_t gofs = (size_t)(kt0 + r) * C3 + c4 * 4;
            float4 kv = *(const float4*)&Kbase[gofs];
            float4 hi, lo; split4(kv, hi, lo);
            int o = c4 * AT_PANEL + r * 4;
            *(float4*)&Kh[o] = hi;
            *(float4*)&Kl[o] = lo;
            *(float4*)&Vsh[r * 68 + c4 * 4] = *(const float4*)&Vbase[gofs];
        }
        __syncthreads();

        // ---- QK via 3xTF32 mma: P[64,64] ----
        float pacc[4][4];
        #pragma unroll
        for (int nt = 0; nt < 4; nt++)
            #pragma unroll
            for (int i = 0; i < 4; i++) pacc[nt][i] = 0.f;

        #pragma unroll
        for (int ks = 0; ks < 8; ks++) {
            const int p0o = (2 * ks) * AT_PANEL;
            const int p1o = p0o + AT_PANEL;
            uint32_t qh[4], ql[4];
            qh[0] = __float_as_uint(Qh[p0o + (mbase + grp) * 4 + qt]);
            qh[1] = __float_as_uint(Qh[p0o + (mbase + grp + 8) * 4 + qt]);
            qh[2] = __float_as_uint(Qh[p1o + (mbase + grp) * 4 + qt]);
            qh[3] = __float_as_uint(Qh[p1o + (mbase + grp + 8) * 4 + qt]);
            ql[0] = __float_as_uint(Ql[p0o + (mbase + grp) * 4 + qt]);
            ql[1] = __float_as_uint(Ql[p0o + (mbase + grp + 8) * 4 + qt]);
            ql[2] = __float_as_uint(Ql[p1o + (mbase + grp) * 4 + qt]);
            ql[3] = __float_as_uint(Ql[p1o + (mbase + grp + 8) * 4 + qt]);
            #pragma unroll
            for (int nt = 0; nt < 4; nt++) {
                const int krow = (nbase + nt * 8 + grp) * 4 + qt;
                uint32_t kh2[2] = { __float_as_uint(Kh[p0o + krow]),
                                    __float_as_uint(Kh[p1o + krow]) };
                uint32_t kl2[2] = { __float_as_uint(Kl[p0o + krow]),
                                    __float_as_uint(Kl[p1o + krow]) };
                mma_tf32(pacc[nt], qh, kh2);
                mma_tf32(pacc[nt], ql, kh2);
                mma_tf32(pacc[nt], qh, kl2);
            }
        }
        // write P fragments to SMEM (stride 72: conflict-free STS.64)
        #pragma unroll
        for (int nt = 0; nt < 4; nt++) {
            const int col = nbase + nt * 8 + 2 * qt;
            const int row = mbase + grp;
            *(float2*)&Psh[row * 72 + col]       = make_float2(pacc[nt][0], pacc[nt][1]);
            *(float2*)&Psh[(row + 8) * 72 + col] = make_float2(pacc[nt][2], pacc[nt][3]);
        }
        __syncthreads();

        // ---- sigmoid pair-scan + shifted exp (warp w owns queries w*8..w*8+7) ----
        float alpha_g[8];
        #pragma unroll
        for (int g = 0; g < 8; g++) {
            const int qq = w * 8 + g;
            const int q  = qbase + qq;
            const int key0 = kt0 + 2 * lane;
            const bool v0 = (key0 <= q), v1 = (key0 + 1 <= q);
            float2 pv = *(const float2*)&Psh[qq * 72 + 2 * lane];
            const float P0 = pv.x * scale;
            const float P1 = pv.y * scale;
            const float s0 = v0 ? __fdividef(1.0f, 1.0f + __expf(-P0)) : 0.f;
            const float s1 = v1 ? __fdividef(1.0f, 1.0f + __expf(-P1)) : 0.f;

            float sp = s0 + s1;
            float sc = sp;
            #pragma unroll
            for (int off = 1; off < 32; off <<= 1) {
                float tv = __shfl_up_sync(0xffffffffu, sc, off);
                if (lane >= off) sc += tv;
            }
            const float tot  = __shfl_sync(0xffffffffu, sc, 31);
            const float excl = sc - sp;

            const float c0 = excl - tot - 8.0f;
            const float e0 = v0 ? __expf(P0 + c0)      : 0.f;
            const float e1 = v1 ? __expf(P1 + c0 + s0) : 0.f;
            const float al = __expf(-tot);
            denl[g] = denl[g] * al + e0 + e1;
            alpha_g[g] = al;
            *(float2*)&esh[qq * 64 + 2 * lane] = make_float2(e0, e1);
        }
        __syncwarp();

        // ---- AV scalar: V tile read once per warp, reused across 8 queries ----
        #pragma unroll
        for (int g = 0; g < 8; g++) { y0[g] *= alpha_g[g]; y1[g] *= alpha_g[g]; }
        #pragma unroll
        for (int k4 = 0; k4 < 16; k4++) {
            float2 v0 = *(const float2*)&Vsh[(k4 * 4 + 0) * 68 + d0];
            float2 v1 = *(const float2*)&Vsh[(k4 * 4 + 1) * 68 + d0];
            float2 v2 = *(const float2*)&Vsh[(k4 * 4 + 2) * 68 + d0];
            float2 v3 = *(const float2*)&Vsh[(k4 * 4 + 3) * 68 + d0];
            #pragma unroll
            for (int g = 0; g < 8; g++) {
                float4 ev = *(const float4*)&esh[(w * 8 + g) * 64 + k4 * 4];
                y0[g] += ev.x * v0.x + ev.y * v1.x + ev.z * v2.x + ev.w * v3.x;
                y1[g] += ev.x * v0.y + ev.y * v1.y + ev.z * v2.y + ev.w * v3.y;
            }
        }
        __syncwarp();
    }

    #pragma unroll
    for (int g = 0; g < 8; g++) {
        float dsum = denl[g];
        #pragma unroll
        for (int off = 16; off; off >>= 1)
            dsum += __shfl_xor_sync(0xffffffffu, dsum, off);
        const float inv = 1.0f / dsum;
        const int q = qbase + w * 8 + g;
        float* yp = yout + (size_t)(b * T_SEQ + q) * CDIM + h * DHEAD + d0;
        *(float2*)yp = make_float2(y0[g] * inv, y1[g] * inv);
    }
}

// ---------------------------------------------------------------------------
extern "C" void kernel_launch(void* const* d_in, const int* in_sizes, int n_in,
                              void* d_out, int out_size)
{
    const float* x = nullptr; const float* Wa = nullptr; const float* Wp = nullptr;
    for (int i = 0; i < n_in; i++) {
        if (in_sizes[i] == BATCH * T_SEQ * CDIM)  x  = (const float*)d_in[i];
        else if (in_sizes[i] == C3 * CDIM)        Wa = (const float*)d_in[i];
        else if (in_sizes[i] == CDIM * CDIM)      Wp = (const float*)d_in[i];
    }
    float* out = (float*)d_out;

    void* qkv_p = nullptr; void* y_p = nullptr;
    cudaGetSymbolAddress(&qkv_p, g_qkv);
    cudaGetSymbolAddress(&y_p,   g_y);
    float* qkv = (float*)qkv_p;
    float* y   = (float*)y_p;

    const int GEMM_SMEM = 2 * GS_BUF * 4;     // 66,560 B
    const int ATTN_SMEM = AT_TOTAL * 4;       // 120,832 B -> 1 CTA/SM
    cudaFuncSetAttribute(gemm_tf32_kernel, cudaFuncAttributeMaxDynamicSharedMemorySize, GEMM_SMEM);
    cudaFuncSetAttribute(attn_kernel,      cudaFuncAttributeMaxDynamicSharedMemorySize, ATTN_SMEM);

    {   // qkv = x @ W_attn^T
        dim3 grid(C3 / 128, MROWS / 128);
        gemm_tf32_kernel<<<grid, 256, GEMM_SMEM>>>(x, Wa, qkv, MROWS, C3, CDIM);
    }
    {   // penalized attention
        dim3 grid(T_SEQ / 64, HEADS, BATCH);
        attn_kernel<<<grid, 256, ATTN_SMEM>>>(qkv, y);
    }
    {   // out = y @ W_proj^T
        dim3 grid(CDIM / 128, MROWS / 128);
        gemm_tf32_kernel<<<grid, 256, GEMM_SMEM>>>(y, Wp, out, MROWS, CDIM, CDIM);
    }
}

// round 15
// speedup vs baseline: 1.8152x; 1.8152x over previous
#include <cuda_runtime.h>
#include <math.h>
#include <stdint.h>

#define BATCH   2
#define T_SEQ   2048
#define CDIM    1024
#define HEADS   16
#define DHEAD   64
#define C3      3072
#define MROWS   4096

__device__ float g_qkv[(size_t)MROWS * C3];   // 48 MB
__device__ float g_y  [(size_t)MROWS * CDIM]; // 16 MB

// ---- tf32 helpers ----------------------------------------------------------
__device__ __forceinline__ uint32_t f2tf32(float x) {
    uint32_t u; asm("cvt.rna.tf32.f32 %0, %1;" : "=r"(u) : "f"(x)); return u;
}
__device__ __forceinline__ void mma_tf32(float* d, const uint32_t* a, const uint32_t* b) {
    asm volatile("mma.sync.aligned.m16n8k8.row.col.f32.tf32.tf32.f32 "
        "{%0,%1,%2,%3}, {%4,%5,%6,%7}, {%8,%9}, {%0,%1,%2,%3};"
        : "+f"(d[0]), "+f"(d[1]), "+f"(d[2]), "+f"(d[3])
        : "r"(a[0]), "r"(a[1]), "r"(a[2]), "r"(a[3]), "r"(b[0]), "r"(b[1]));
}
// split float4 -> tf32 hi/lo float4s
__device__ __forceinline__ void split4(float4 v, float4& h, float4& l) {
    uint32_t hx = f2tf32(v.x), hy = f2tf32(v.y), hz = f2tf32(v.z), hw = f2tf32(v.w);
    h = make_float4(__uint_as_float(hx), __uint_as_float(hy),
                    __uint_as_float(hz), __uint_as_float(hw));
    l = make_float4(__uint_as_float(f2tf32(v.x - __uint_as_float(hx))),
                    __uint_as_float(f2tf32(v.y - __uint_as_float(hy))),
                    __uint_as_float(f2tf32(v.z - __uint_as_float(hz))),
                    __uint_as_float(f2tf32(v.w - __uint_as_float(hw))));
}

// ---------------------------------------------------------------------------
// NT GEMM on tensor cores (exact R11 version, measured 438us at normal clock).
// ---------------------------------------------------------------------------
#define GS_PANEL 520
#define GS_A_HI  0
#define GS_A_LO  (4 * GS_PANEL)
#define GS_B_HI  (8 * GS_PANEL)
#define GS_B_LO  (12 * GS_PANEL)
#define GS_BUF   (16 * GS_PANEL)

__global__ void __launch_bounds__(256, 2)
gemm_tf32_kernel(const float* __restrict__ A,
                 const float* __restrict__ B,
                 float* __restrict__ C,
                 int M, int N, int K)
{
    extern __shared__ __align__(16) float gsm[];

    const int t    = threadIdx.x;
    const int lane = t & 31;
    const int w    = t >> 5;
    const int wm   = w >> 2;
    const int wn   = w & 3;
    const int grp  = lane >> 2;
    const int qt   = lane & 3;
    const int m0   = blockIdx.y * 128;
    const int n0   = blockIdx.x * 128;

    const int srow = t >> 2;
    const int sc4  = t & 3;

    float acc[4][4][4];
    #pragma unroll
    for (int mt = 0; mt < 4; mt++)
        #pragma unroll
        for (int nt = 0; nt < 4; nt++)
            #pragma unroll
            for (int i = 0; i < 4; i++) acc[mt][nt][i] = 0.f;

    const float* Ap0 = A + (size_t)(m0 + srow)      * K + sc4 * 4;
    const float* Ap1 = A + (size_t)(m0 + srow + 64) * K + sc4 * 4;
    const float* Bp0 = B + (size_t)(n0 + srow)      * K + sc4 * 4;
    const float* Bp1 = B + (size_t)(n0 + srow + 64) * K + sc4 * 4;

    auto stage = [&](float4 va0, float4 va1, float4 vb0, float4 vb1, int buf) {
        float* bb = gsm + buf * GS_BUF;
        const int off0 = sc4 * GS_PANEL + srow * 4;
        const int off1 = off0 + 256;
        float4 h, l;
        split4(va0, h, l); *(float4*)&bb[GS_A_HI + off0] = h; *(float4*)&bb[GS_A_LO + off0] = l;
        split4(va1, h, l); *(float4*)&bb[GS_A_HI + off1] = h; *(float4*)&bb[GS_A_LO + off1] = l;
        split4(vb0, h, l); *(float4*)&bb[GS_B_HI + off0] = h; *(float4*)&bb[GS_B_LO + off0] = l;
        split4(vb1, h, l); *(float4*)&bb[GS_B_HI + off1] = h; *(float4*)&bb[GS_B_LO + off1] = l;
    };

    float4 va0 = *(const float4*)Ap0, va1 = *(const float4*)Ap1;
    float4 vb0 = *(const float4*)Bp0, vb1 = *(const float4*)Bp1;
    stage(va0, va1, vb0, vb1, 0);
    __syncthreads();

    const int abase = (wm * 64 + grp) * 4 + qt;
    const int bbase = (wn * 32 + grp) * 4 + qt;

    const int nch = K / 16;
    for (int ch = 0; ch < nch; ch++) {
        const bool has = (ch + 1 < nch);
        if (has) {
            va0 = *(const float4*)(Ap0 + (ch + 1) * 16);
            va1 = *(const float4*)(Ap1 + (ch + 1) * 16);
            vb0 = *(const float4*)(Bp0 + (ch + 1) * 16);
            vb1 = *(const float4*)(Bp1 + (ch + 1) * 16);
        }

        const float* Sb = gsm + (ch & 1) * GS_BUF;
        #pragma unroll
        for (int kg = 0; kg < 2; kg++) {
            const int pk = kg * 2 * GS_PANEL;
            uint32_t bh[4][2], bl[4][2];
            #pragma unroll
            for (int nt = 0; nt < 4; nt++) {
                const int o = pk + bbase + nt * 32;
                bh[nt][0] = __float_as_uint(Sb[GS_B_HI + o]);
                bh[nt][1] = __float_as_uint(Sb[GS_B_HI + o + GS_PANEL]);
                bl[nt][0] = __float_as_uint(Sb[GS_B_LO + o]);
                bl[nt][1] = __float_as_uint(Sb[GS_B_LO + o + GS_PANEL]);
            }
            #pragma unroll
            for (int mt = 0; mt < 4; mt++) {
                const int o = pk + abase + mt * 64;
                uint32_t ah[4], al[4];
                ah[0] = __float_as_uint(Sb[GS_A_HI + o]);
                ah[1] = __float_as_uint(Sb[GS_A_HI + o + 32]);
                ah[2] = __float_as_uint(Sb[GS_A_HI + o + GS_PANEL]);
                ah[3] = __float_as_uint(Sb[GS_A_HI + o + GS_PANEL + 32]);
                al[0] = __float_as_uint(Sb[GS_A_LO + o]);
                al[1] = __float_as_uint(Sb[GS_A_LO + o + 32]);
                al[2] = __float_as_uint(Sb[GS_A_LO + o + GS_PANEL]);
                al[3] = __float_as_uint(Sb[GS_A_LO + o + GS_PANEL + 32]);
                #pragma unroll
                for (int nt = 0; nt < 4; nt++) {
                    mma_tf32(acc[mt][nt], ah, bh[nt]);
                    mma_tf32(acc[mt][nt], al, bh[nt]);
                    mma_tf32(acc[mt][nt], ah, bl[nt]);
                }
            }
        }
        __syncthreads();
        if (has) {
            stage(va0, va1, vb0, vb1, (ch + 1) & 1);
            __syncthreads();
        }
    }

    #pragma unroll
    for (int mt = 0; mt < 4; mt++) {
        #pragma unroll
        for (int nt = 0; nt < 4; nt++) {
            const int row = m0 + wm * 64 + mt * 16 + grp;
            const int col = n0 + wn * 32 + nt * 8 + qt * 2;
            *(float2*)&C[(size_t)row * N + col]       = make_float2(acc[mt][nt][0], acc[mt][nt][1]);
            *(float2*)&C[(size_t)(row + 8) * N + col] = make_float2(acc[mt][nt][2], acc[mt][nt][3]);
        }
    }
}

// ---------------------------------------------------------------------------
// Penalized attention with TENSOR-CORE QK, now at 2 CTAs/SM.
// softmax(P - Z) == softmax(P[k] + prefix_excl_sigmoid(k)).
// Per 64q x 64k tile: P = Q@K^T via 3xTF32 mma -> P to SMEM -> sigmoid
// pair-scan + shifted exp -> e written IN-PLACE into Psh (same warp produces
// and consumes those rows; cross-warp edges covered by existing barriers)
// -> AV scalar. 104.4 KB smem -> 2 CTAs/SM (the R14 regression was the
// 1-CTA/SM config fully exposing the 3 per-tile barriers).
// ---------------------------------------------------------------------------
#define AT_PANEL 268
#define AT_QH    0
#define AT_QL    (16 * AT_PANEL)          // 4288
#define AT_KH    (32 * AT_PANEL)          // 8576
#define AT_KL    (48 * AT_PANEL)          // 12864
#define AT_V     (64 * AT_PANEL)          // 17152  (64 x 68)
#define AT_P     (AT_V + 64 * 68)         // 21504  (64 x 72; e reuses this)
#define AT_TOTAL (AT_P + 64 * 72)         // 26112 floats = 104448 B

__global__ void __launch_bounds__(256, 2)
attn_kernel(const float* __restrict__ qkv, float* __restrict__ yout)
{
    extern __shared__ __align__(16) float sm[];
    float* Qh  = sm + AT_QH;
    float* Ql  = sm + AT_QL;
    float* Kh  = sm + AT_KH;
    float* Kl  = sm + AT_KL;
    float* Vsh = sm + AT_V;
    float* Psh = sm + AT_P;               // P on entry to scan; e afterwards

    const int b     = blockIdx.z;
    const int h     = blockIdx.y;
    const int qbase = (int)(gridDim.x - 1 - blockIdx.x) * 64;  // longest first
    const int w     = threadIdx.x >> 5;
    const int lane  = threadIdx.x & 31;
    const int grp   = lane >> 2;
    const int qt    = lane & 3;
    const int d0    = 2 * lane;
    const float scale = 0.125f;

    // ---- stage Q panels hi/lo (once per block) ----
    #pragma unroll
    for (int i = 0; i < 4; i++) {
        int idx = threadIdx.x + i * 256;
        int r = idx >> 4, c4 = idx & 15;
        const float* qptr = qkv + (size_t)(b * T_SEQ + qbase + r) * C3 + h * DHEAD + c4 * 4;
        float4 v = *(const float4*)qptr;
        float4 hi, lo; split4(v, hi, lo);
        int o = c4 * AT_PANEL + r * 4;
        *(float4*)&Qh[o] = hi;
        *(float4*)&Ql[o] = lo;
    }

    const float* Kbase = qkv + (size_t)(b * T_SEQ) * C3 + CDIM     + h * DHEAD;
    const float* Vbase = qkv + (size_t)(b * T_SEQ) * C3 + 2 * CDIM + h * DHEAD;
    const int ntiles = (qbase >> 6) + 1;

    float denl[8], y0[8], y1[8];
    #pragma unroll
    for (int g = 0; g < 8; g++) { denl[g] = 0.f; y0[g] = 0.f; y1[g] = 0.f; }

    const int mbase = (w & 3) * 16;     // mma query-row tile
    const int nbase = (w >> 2) * 32;    // mma key-col tile

    for (int tile = 0; tile < ntiles; tile++) {
        const int kt0 = tile << 6;
        __syncthreads();   // prev AV (e reads) done; also covers Q staging

        // ---- stage K panels hi/lo + V plain ----
        #pragma unroll
        for (int i = 0; i < 4; i++) {
            int idx = threadIdx.x + i * 256;
            int r = idx >> 4, c4 = idx & 15;
            size_t gofs = (size_t)(kt0 + r) * C3 + c4 * 4;
            float4 kv = *(const float4*)&Kbase[gofs];
            float4 hi, lo; split4(kv, hi, lo);
            int o = c4 * AT_PANEL + r * 4;
            *(float4*)&Kh[o] = hi;
            *(float4*)&Kl[o] = lo;
            *(float4*)&Vsh[r * 68 + c4 * 4] = *(const float4*)&Vbase[gofs];
        }
        __syncthreads();

        // ---- QK via 3xTF32 mma: P[64,64] ----
        float pacc[4][4];
        #pragma unroll
        for (int nt = 0; nt < 4; nt++)
            #pragma unroll
            for (int i = 0; i < 4; i++) pacc[nt][i] = 0.f;

        #pragma unroll
        for (int ks = 0; ks < 8; ks++) {
            const int p0o = (2 * ks) * AT_PANEL;
            const int p1o = p0o + AT_PANEL;
            uint32_t qh[4], ql[4];
            qh[0] = __float_as_uint(Qh[p0o + (mbase + grp) * 4 + qt]);
            qh[1] = __float_as_uint(Qh[p0o + (mbase + grp + 8) * 4 + qt]);
            qh[2] = __float_as_uint(Qh[p1o + (mbase + grp) * 4 + qt]);
            qh[3] = __float_as_uint(Qh[p1o + (mbase + grp + 8) * 4 + qt]);
            ql[0] = __float_as_uint(Ql[p0o + (mbase + grp) * 4 + qt]);
            ql[1] = __float_as_uint(Ql[p0o + (mbase + grp + 8) * 4 + qt]);
            ql[2] = __float_as_uint(Ql[p1o + (mbase + grp) * 4 + qt]);
            ql[3] = __float_as_uint(Ql[p1o + (mbase + grp + 8) * 4 + qt]);
            #pragma unroll
            for (int nt = 0; nt < 4; nt++) {
                const int krow = (nbase + nt * 8 + grp) * 4 + qt;
                uint32_t kh2[2] = { __float_as_uint(Kh[p0o + krow]),
                                    __float_as_uint(Kh[p1o + krow]) };
                uint32_t kl2[2] = { __float_as_uint(Kl[p0o + krow]),
                                    __float_as_uint(Kl[p1o + krow]) };
                mma_tf32(pacc[nt], qh, kh2);
                mma_tf32(pacc[nt], ql, kh2);
                mma_tf32(pacc[nt], qh, kl2);
            }
        }
        // write P fragments to SMEM (stride 72)
        #pragma unroll
        for (int nt = 0; nt < 4; nt++) {
            const int col = nbase + nt * 8 + 2 * qt;
            const int row = mbase + grp;
            *(float2*)&Psh[row * 72 + col]       = make_float2(pacc[nt][0], pacc[nt][1]);
            *(float2*)&Psh[(row + 8) * 72 + col] = make_float2(pacc[nt][2], pacc[nt][3]);
        }
        __syncthreads();

        // ---- sigmoid pair-scan + shifted exp; e overwrites P in-place ----
        float alpha_g[8];
        #pragma unroll
        for (int g = 0; g < 8; g++) {
            const int qq = w * 8 + g;
            const int q  = qbase + qq;
            const int key0 = kt0 + 2 * lane;
            const bool v0 = (key0 <= q), v1 = (key0 + 1 <= q);
            float2 pv = *(const float2*)&Psh[qq * 72 + 2 * lane];
            const float P0 = pv.x * scale;
            const float P1 = pv.y * scale;
            const float s0 = v0 ? __fdividef(1.0f, 1.0f + __expf(-P0)) : 0.f;
            const float s1 = v1 ? __fdividef(1.0f, 1.0f + __expf(-P1)) : 0.f;

            float sp = s0 + s1;
            float sc = sp;
            #pragma unroll
            for (int off = 1; off < 32; off <<= 1) {
                float tv = __shfl_up_sync(0xffffffffu, sc, off);
                if (lane >= off) sc += tv;
            }
            const float tot  = __shfl_sync(0xffffffffu, sc, 31);
            const float excl = sc - sp;

            const float c0 = excl - tot - 8.0f;
            const float e0 = v0 ? __expf(P0 + c0)      : 0.f;
            const float e1 = v1 ? __expf(P1 + c0 + s0) : 0.f;
            const float al = __expf(-tot);
            denl[g] = denl[g] * al + e0 + e1;
            alpha_g[g] = al;
            // in-place: same warp read this row above; same warp reads e below
            *(float2*)&Psh[qq * 72 + 2 * lane] = make_float2(e0, e1);
        }
        __syncwarp();

        // ---- AV scalar: V tile read once per warp, reused across 8 queries ----
        #pragma unroll
        for (int g = 0; g < 8; g++) { y0[g] *= alpha_g[g]; y1[g] *= alpha_g[g]; }
        #pragma unroll
        for (int k4 = 0; k4 < 16; k4++) {
            float2 v0 = *(const float2*)&Vsh[(k4 * 4 + 0) * 68 + d0];
            float2 v1 = *(const float2*)&Vsh[(k4 * 4 + 1) * 68 + d0];
            float2 v2 = *(const float2*)&Vsh[(k4 * 4 + 2) * 68 + d0];
            float2 v3 = *(const float2*)&Vsh[(k4 * 4 + 3) * 68 + d0];
            #pragma unroll
            for (int g = 0; g < 8; g++) {
                float4 ev = *(const float4*)&Psh[(w * 8 + g) * 72 + k4 * 4];
                y0[g] += ev.x * v0.x + ev.y * v1.x + ev.z * v2.x + ev.w * v3.x;
                y1[g] += ev.x * v0.y + ev.y * v1.y + ev.z * v2.y + ev.w * v3.y;
            }
        }
        __syncwarp();
    }

    #pragma unroll
    for (int g = 0; g < 8; g++) {
        float dsum = denl[g];
        #pragma unroll
        for (int off = 16; off; off >>= 1)
            dsum += __shfl_xor_sync(0xffffffffu, dsum, off);
        const float inv = 1.0f / dsum;
        const int q = qbase + w * 8 + g;
        float* yp = yout + (size_t)(b * T_SEQ + q) * CDIM + h * DHEAD + d0;
        *(float2*)yp = make_float2(y0[g] * inv, y1[g] * inv);
    }
}

// ---------------------------------------------------------------------------
extern "C" void kernel_launch(void* const* d_in, const int* in_sizes, int n_in,
                              void* d_out, int out_size)
{
    const float* x = nullptr; const float* Wa = nullptr; const float* Wp = nullptr;
    for (int i = 0; i < n_in; i++) {
        if (in_sizes[i] == BATCH * T_SEQ * CDIM)  x  = (const float*)d_in[i];
        else if (in_sizes[i] == C3 * CDIM)        Wa = (const float*)d_in[i];
        else if (in_sizes[i] == CDIM * CDIM)      Wp = (const float*)d_in[i];
    }
    float* out = (float*)d_out;

    void* qkv_p = nullptr; void* y_p = nullptr;
    cudaGetSymbolAddress(&qkv_p, g_qkv);
    cudaGetSymbolAddress(&y_p,   g_y);
    float* qkv = (float*)qkv_p;
    float* y   = (float*)y_p;

    const int GEMM_SMEM = 2 * GS_BUF * 4;     // 66,560 B
    const int ATTN_SMEM = AT_TOTAL * 4;       // 104,448 B -> 2 CTAs/SM
    cudaFuncSetAttribute(gemm_tf32_kernel, cudaFuncAttributeMaxDynamicSharedMemorySize, GEMM_SMEM);
    cudaFuncSetAttribute(attn_kernel,      cudaFuncAttributeMaxDynamicSharedMemorySize, ATTN_SMEM);

    {   // qkv = x @ W_attn^T
        dim3 grid(C3 / 128, MROWS / 128);
        gemm_tf32_kernel<<<grid, 256, GEMM_SMEM>>>(x, Wa, qkv, MROWS, C3, CDIM);
    }
    {   // penalized attention
        dim3 grid(T_SEQ / 64, HEADS, BATCH);
        attn_kernel<<<grid, 256, ATTN_SMEM>>>(qkv, y);
    }
    {   // out = y @ W_proj^T
        dim3 grid(CDIM / 128, MROWS / 128);
        gemm_tf32_kernel<<<grid, 256, GEMM_SMEM>>>(y, Wp, out, MROWS, CDIM, CDIM);
    }
}

// round 17
// speedup vs baseline: 1.8303x; 1.0083x over previous
#include <cuda_runtime.h>
#include <math.h>
#include <stdint.h>

#define BATCH   2
#define T_SEQ   2048
#define CDIM    1024
#define HEADS   16
#define DHEAD   64
#define C3      3072
#define MROWS   4096

__device__ float g_qkv[(size_t)MROWS * C3];   // 48 MB
__device__ float g_vt [(size_t)MROWS * CDIM]; // 16 MB  V transposed [b][h][dim][t]
__device__ float g_y  [(size_t)MROWS * CDIM]; // 16 MB

// ---- tf32 helpers ----------------------------------------------------------
__device__ __forceinline__ uint32_t f2tf32(float x) {
    uint32_t u; asm("cvt.rna.tf32.f32 %0, %1;" : "=r"(u) : "f"(x)); return u;
}
__device__ __forceinline__ void mma_tf32(float* d, const uint32_t* a, const uint32_t* b) {
    asm volatile("mma.sync.aligned.m16n8k8.row.col.f32.tf32.tf32.f32 "
        "{%0,%1,%2,%3}, {%4,%5,%6,%7}, {%8,%9}, {%0,%1,%2,%3};"
        : "+f"(d[0]), "+f"(d[1]), "+f"(d[2]), "+f"(d[3])
        : "r"(a[0]), "r"(a[1]), "r"(a[2]), "r"(a[3]), "r"(b[0]), "r"(b[1]));
}
__device__ __forceinline__ void split4(float4 v, float4& h, float4& l) {
    uint32_t hx = f2tf32(v.x), hy = f2tf32(v.y), hz = f2tf32(v.z), hw = f2tf32(v.w);
    h = make_float4(__uint_as_float(hx), __uint_as_float(hy),
                    __uint_as_float(hz), __uint_as_float(hw));
    l = make_float4(__uint_as_float(f2tf32(v.x - __uint_as_float(hx))),
                    __uint_as_float(f2tf32(v.y - __uint_as_float(hy))),
                    __uint_as_float(f2tf32(v.z - __uint_as_float(hz))),
                    __uint_as_float(f2tf32(v.w - __uint_as_float(hw))));
}
__device__ __forceinline__ void split1(float v, float& h, float& l) {
    uint32_t hx = f2tf32(v);
    h = __uint_as_float(hx);
    l = __uint_as_float(f2tf32(v - h));
}

// ---------------------------------------------------------------------------
// NT GEMM on tensor cores (R11 core, measured 438us) + optional V-transpose
// epilogue redirect: columns >= 2C go to VT[b][h][dim][token] instead of C.
// ---------------------------------------------------------------------------
#define GS_PANEL 520
#define GS_A_HI  0
#define GS_A_LO  (4 * GS_PANEL)
#define GS_B_HI  (8 * GS_PANEL)
#define GS_B_LO  (12 * GS_PANEL)
#define GS_BUF   (16 * GS_PANEL)

__global__ void __launch_bounds__(256, 2)
gemm_tf32_kernel(const float* __restrict__ A,
                 const float* __restrict__ B,
                 float* __restrict__ C,
                 int M, int N, int K,
                 float* __restrict__ VT)
{
    extern __shared__ __align__(16) float gsm[];

    const int t    = threadIdx.x;
    const int lane = t & 31;
    const int w    = t >> 5;
    const int wm   = w >> 2;
    const int wn   = w & 3;
    const int grp  = lane >> 2;
    const int qt   = lane & 3;
    const int m0   = blockIdx.y * 128;
    const int n0   = blockIdx.x * 128;

    const int srow = t >> 2;
    const int sc4  = t & 3;

    float acc[4][4][4];
    #pragma unroll
    for (int mt = 0; mt < 4; mt++)
        #pragma unroll
        for (int nt = 0; nt < 4; nt++)
            #pragma unroll
            for (int i = 0; i < 4; i++) acc[mt][nt][i] = 0.f;

    const float* Ap0 = A + (size_t)(m0 + srow)      * K + sc4 * 4;
    const float* Ap1 = A + (size_t)(m0 + srow + 64) * K + sc4 * 4;
    const float* Bp0 = B + (size_t)(n0 + srow)      * K + sc4 * 4;
    const float* Bp1 = B + (size_t)(n0 + srow + 64) * K + sc4 * 4;

    auto stage = [&](float4 va0, float4 va1, float4 vb0, float4 vb1, int buf) {
        float* bb = gsm + buf * GS_BUF;
        const int off0 = sc4 * GS_PANEL + srow * 4;
        const int off1 = off0 + 256;
        float4 h, l;
        split4(va0, h, l); *(float4*)&bb[GS_A_HI + off0] = h; *(float4*)&bb[GS_A_LO + off0] = l;
        split4(va1, h, l); *(float4*)&bb[GS_A_HI + off1] = h; *(float4*)&bb[GS_A_LO + off1] = l;
        split4(vb0, h, l); *(float4*)&bb[GS_B_HI + off0] = h; *(float4*)&bb[GS_B_LO + off0] = l;
        split4(vb1, h, l); *(float4*)&bb[GS_B_HI + off1] = h; *(float4*)&bb[GS_B_LO + off1] = l;
    };

    float4 va0 = *(const float4*)Ap0, va1 = *(const float4*)Ap1;
    float4 vb0 = *(const float4*)Bp0, vb1 = *(const float4*)Bp1;
    stage(va0, va1, vb0, vb1, 0);
    __syncthreads();

    const int abase = (wm * 64 + grp) * 4 + qt;
    const int bbase = (wn * 32 + grp) * 4 + qt;

    const int nch = K / 16;
    for (int ch = 0; ch < nch; ch++) {
        const bool has = (ch + 1 < nch);
        if (has) {
            va0 = *(const float4*)(Ap0 + (ch + 1) * 16);
            va1 = *(const float4*)(Ap1 + (ch + 1) * 16);
            vb0 = *(const float4*)(Bp0 + (ch + 1) * 16);
            vb1 = *(const float4*)(Bp1 + (ch + 1) * 16);
        }

        const float* Sb = gsm + (ch & 1) * GS_BUF;
        #pragma unroll
        for (int kg = 0; kg < 2; kg++) {
            const int pk = kg * 2 * GS_PANEL;
            uint32_t bh[4][2], bl[4][2];
            #pragma unroll
            for (int nt = 0; nt < 4; nt++) {
                const int o = pk + bbase + nt * 32;
                bh[nt][0] = __float_as_uint(Sb[GS_B_HI + o]);
                bh[nt][1] = __float_as_uint(Sb[GS_B_HI + o + GS_PANEL]);
                bl[nt][0] = __float_as_uint(Sb[GS_B_LO + o]);
                bl[nt][1] = __float_as_uint(Sb[GS_B_LO + o + GS_PANEL]);
            }
            #pragma unroll
            for (int mt = 0; mt < 4; mt++) {
                const int o = pk + abase + mt * 64;
                uint32_t ah[4], al[4];
                ah[0] = __float_as_uint(Sb[GS_A_HI + o]);
                ah[1] = __float_as_uint(Sb[GS_A_HI + o + 32]);
                ah[2] = __float_as_uint(Sb[GS_A_HI + o + GS_PANEL]);
                ah[3] = __float_as_uint(Sb[GS_A_HI + o + GS_PANEL + 32]);
                al[0] = __float_as_uint(Sb[GS_A_LO + o]);
                al[1] = __float_as_uint(Sb[GS_A_LO + o + 32]);
                al[2] = __float_as_uint(Sb[GS_A_LO + o + GS_PANEL]);
                al[3] = __float_as_uint(Sb[GS_A_LO + o + GS_PANEL + 32]);
                #pragma unroll
                for (int nt = 0; nt < 4; nt++) {
                    mma_tf32(acc[mt][nt], ah, bh[nt]);
                    mma_tf32(acc[mt][nt], al, bh[nt]);
                    mma_tf32(acc[mt][nt], ah, bl[nt]);
                }
            }
        }
        __syncthreads();
        if (has) {
            stage(va0, va1, vb0, vb1, (ch + 1) & 1);
            __syncthreads();
        }
    }

    const bool vpart = (VT != nullptr) && (n0 >= 2 * CDIM);
    #pragma unroll
    for (int mt = 0; mt < 4; mt++) {
        #pragma unroll
        for (int nt = 0; nt < 4; nt++) {
            const int row = m0 + wm * 64 + mt * 16 + grp;
            const int col = n0 + wn * 32 + nt * 8 + qt * 2;
            if (vpart) {
                const int vcol = col - 2 * CDIM;
                const int hh = vcol >> 6, dim = vcol & 63;
                const int bb = row >> 11, tt = row & 2047;
                size_t base = ((size_t)(bb * HEADS + hh) * DHEAD + dim) * T_SEQ + tt;
                VT[base]             = acc[mt][nt][0];
                VT[base + T_SEQ]     = acc[mt][nt][1];
                VT[base + 8]         = acc[mt][nt][2];
                VT[base + T_SEQ + 8] = acc[mt][nt][3];
            } else {
                *(float2*)&C[(size_t)row * N + col]       = make_float2(acc[mt][nt][0], acc[mt][nt][1]);
                *(float2*)&C[(size_t)(row + 8) * N + col] = make_float2(acc[mt][nt][2], acc[mt][nt][3]);
            }
        }
    }
}

// ---------------------------------------------------------------------------
// Penalized attention: tensor-core QK AND AV (3xTF32), 512 thr / 16 warps.
// softmax(P - Z) == softmax(P[k] + prefix_excl_sigmoid(k)).
// Per 64q x 64k tile:
//   P = Q@K^T (mma) -> Psh -> sigmoid pair-scan + shifted exp ->
//   e written as tf32 hi/lo PANELS + alpha[64] -> Y += e@V^T via mma with
//   per-row alpha rescale of the Y accumulators (flash-style).
// V^T comes pre-transposed from the QKV GEMM epilogue (g_vt).
// smem 156.2 KB, 1 CTA/SM (16 warps = same warp count as R15's 2x8).
// ---------------------------------------------------------------------------
#define A2P      268
#define A2_QH    0
#define A2_QL    4288
#define A2_KH    8576
#define A2_KL    12864
#define A2_VH    17152
#define A2_VL    21440
#define A2_P     25728            // 64 x 72
#define A2_EH    30336
#define A2_EL    34624
#define A2_ALPHA 38912            // 64
#define A2_DEN   38976            // 64
#define A2_TOTAL 39040            // floats = 156160 B

__global__ void __launch_bounds__(512, 1)
attn_kernel(const float* __restrict__ qkv, const float* __restrict__ vt,
            float* __restrict__ yout)
{
    extern __shared__ __align__(16) float sm[];
    float* Qh  = sm + A2_QH;
    float* Ql  = sm + A2_QL;
    float* Kh  = sm + A2_KH;
    float* Kl  = sm + A2_KL;
    float* Vh  = sm + A2_VH;
    float* Vl  = sm + A2_VL;
    float* Psh = sm + A2_P;
    float* Eh  = sm + A2_EH;
    float* El  = sm + A2_EL;
    float* alpha_sh = sm + A2_ALPHA;
    float* den_sh   = sm + A2_DEN;

    const int tid  = threadIdx.x;
    const int w    = tid >> 5;
    const int lane = tid & 31;
    const int grp  = lane >> 2;
    const int qt   = lane & 3;
    const int b    = blockIdx.z;
    const int h    = blockIdx.y;
    const int qbase = (int)(gridDim.x - 1 - blockIdx.x) * 64;  // longest first
    const float scale = 0.125f;

    const int mbase = (w & 3) * 16;      // query tile (QK m / AV m)
    const int nbase = (w >> 2) * 16;     // key tile (QK n) / dim tile (AV n)

    // ---- stage Q panels hi/lo (once per block) ----
    #pragma unroll
    for (int i = 0; i < 2; i++) {
        int idx = tid + i * 512;
        int r = idx >> 4, c4 = idx & 15;
        const float* qptr = qkv + (size_t)(b * T_SEQ + qbase + r) * C3 + h * DHEAD + c4 * 4;
        float4 v = *(const float4*)qptr;
        float4 hi, lo; split4(v, hi, lo);
        int o = c4 * A2P + r * 4;
        *(float4*)&Qh[o] = hi;
        *(float4*)&Ql[o] = lo;
    }

    const float* Kbase = qkv + (size_t)(b * T_SEQ) * C3 + CDIM + h * DHEAD;
    const float* Vtb   = vt + (size_t)(b * HEADS + h) * DHEAD * T_SEQ;
    const int ntiles = (qbase >> 6) + 1;

    float denl[4] = {0.f, 0.f, 0.f, 0.f};
    float yacc[2][4];
    #pragma unroll
    for (int nt = 0; nt < 2; nt++)
        #pragma unroll
        for (int i = 0; i < 4; i++) yacc[nt][i] = 0.f;

    for (int tile = 0; tile < ntiles; tile++) {
        const int kt0 = tile << 6;
        __syncthreads();   // prev AV reads of Eh/Vh done; covers Q staging too

        // ---- stage K panels hi/lo + V^T panels hi/lo ----
        #pragma unroll
        for (int i = 0; i < 2; i++) {
            int idx = tid + i * 512;
            int r = idx >> 4, c4 = idx & 15;
            int o = c4 * A2P + r * 4;
            float4 kv = *(const float4*)&Kbase[(size_t)(kt0 + r) * C3 + c4 * 4];
            float4 hi, lo; split4(kv, hi, lo);
            *(float4*)&Kh[o] = hi;
            *(float4*)&Kl[o] = lo;
            float4 vv = *(const float4*)&Vtb[(size_t)r * T_SEQ + kt0 + c4 * 4];
            split4(vv, hi, lo);
            *(float4*)&Vh[o] = hi;
            *(float4*)&Vl[o] = lo;
        }
        __syncthreads();

        // ---- QK via 3xTF32 mma: P[64,64] ----
        float pacc[2][4];
        #pragma unroll
        for (int nt = 0; nt < 2; nt++)
            #pragma unroll
            for (int i = 0; i < 4; i++) pacc[nt][i] = 0.f;

        #pragma unroll
        for (int ks = 0; ks < 8; ks++) {
            const int p0o = (2 * ks) * A2P;
            const int p1o = p0o + A2P;
            const int o = (mbase + grp) * 4 + qt;
            uint32_t qh[4], ql[4];
            qh[0] = __float_as_uint(Qh[p0o + o]);
            qh[1] = __float_as_uint(Qh[p0o + o + 32]);
            qh[2] = __float_as_uint(Qh[p1o + o]);
            qh[3] = __float_as_uint(Qh[p1o + o + 32]);
            ql[0] = __float_as_uint(Ql[p0o + o]);
            ql[1] = __float_as_uint(Ql[p0o + o + 32]);
            ql[2] = __float_as_uint(Ql[p1o + o]);
            ql[3] = __float_as_uint(Ql[p1o + o + 32]);
            #pragma unroll
            for (int nt = 0; nt < 2; nt++) {
                const int krow = (nbase + nt * 8 + grp) * 4 + qt;
                uint32_t kh2[2] = { __float_as_uint(Kh[p0o + krow]),
                                    __float_as_uint(Kh[p1o + krow]) };
                uint32_t kl2[2] = { __float_as_uint(Kl[p0o + krow]),
                                    __float_as_uint(Kl[p1o + krow]) };
                mma_tf32(pacc[nt], qh, kh2);
                mma_tf32(pacc[nt], ql, kh2);
                mma_tf32(pacc[nt], qh, kl2);
            }
        }
        #pragma unroll
        for (int nt = 0; nt < 2; nt++) {
            const int col = nbase + nt * 8 + 2 * qt;
            const int row = mbase + grp;
            *(float2*)&Psh[row * 72 + col]       = make_float2(pacc[nt][0], pacc[nt][1]);
            *(float2*)&Psh[(row + 8) * 72 + col] = make_float2(pacc[nt][2], pacc[nt][3]);
        }
        __syncthreads();

        // ---- sigmoid pair-scan + shifted exp; e -> tf32 hi/lo panels ----
        #pragma unroll
        for (int g = 0; g < 4; g++) {
            const int qq = w * 4 + g;
            const int q  = qbase + qq;
            const int key0 = kt0 + 2 * lane;
            const bool v0 = (key0 <= q), v1 = (key0 + 1 <= q);
            float2 pv = *(const float2*)&Psh[qq * 72 + 2 * lane];
            const float P0 = pv.x * scale;
            const float P1 = pv.y * scale;
            const float s0 = v0 ? __fdividef(1.0f, 1.0f + __expf(-P0)) : 0.f;
            const float s1 = v1 ? __fdividef(1.0f, 1.0f + __expf(-P1)) : 0.f;

            float sp = s0 + s1;
            float sc = sp;
            #pragma unroll
            for (int off = 1; off < 32; off <<= 1) {
                float tv = __shfl_up_sync(0xffffffffu, sc, off);
                if (lane >= off) sc += tv;
            }
            const float tot  = __shfl_sync(0xffffffffu, sc, 31);
            const float excl = sc - sp;

            const float c0 = excl - tot - 8.0f;
            const float e0 = v0 ? __expf(P0 + c0)      : 0.f;
            const float e1 = v1 ? __expf(P1 + c0 + s0) : 0.f;
            const float al = __expf(-tot);
            denl[g] = denl[g] * al + e0 + e1;

            float e0h, e0l, e1h, e1l;
            split1(e0, e0h, e0l);
            split1(e1, e1h, e1l);
            const int ea = (lane >> 1) * A2P + qq * 4 + 2 * (lane & 1);
            *(float2*)&Eh[ea] = make_float2(e0h, e1h);
            *(float2*)&El[ea] = make_float2(e0l, e1l);
            if (lane == g) alpha_sh[qq] = al;
        }
        __syncthreads();

        // ---- AV via 3xTF32 mma with flash-style alpha rescale ----
        {
            const float a0 = alpha_sh[mbase + grp];
            const float a1 = alpha_sh[mbase + grp + 8];
            #pragma unroll
            for (int nt = 0; nt < 2; nt++) {
                yacc[nt][0] *= a0; yacc[nt][1] *= a0;
                yacc[nt][2] *= a1; yacc[nt][3] *= a1;
            }
        }
        #pragma unroll
        for (int ks = 0; ks < 8; ks++) {
            const int p0o = (2 * ks) * A2P;
            const int p1o = p0o + A2P;
            const int o = (mbase + grp) * 4 + qt;
            uint32_t eh[4], el[4];
            eh[0] = __float_as_uint(Eh[p0o + o]);
            eh[1] = __float_as_uint(Eh[p0o + o + 32]);
            eh[2] = __float_as_uint(Eh[p1o + o]);
            eh[3] = __float_as_uint(Eh[p1o + o + 32]);
            el[0] = __float_as_uint(El[p0o + o]);
            el[1] = __float_as_uint(El[p0o + o + 32]);
            el[2] = __float_as_uint(El[p1o + o]);
            el[3] = __float_as_uint(El[p1o + o + 32]);
            #pragma unroll
            for (int nt = 0; nt < 2; nt++) {
                const int vrow = (nbase + nt * 8 + grp) * 4 + qt;
                uint32_t vh2[2] = { __float_as_uint(Vh[p0o + vrow]),
                                    __float_as_uint(Vh[p1o + vrow]) };
                uint32_t vl2[2] = { __float_as_uint(Vl[p0o + vrow]),
                                    __float_as_uint(Vl[p1o + vrow]) };
                mma_tf32(yacc[nt], eh, vh2);
                mma_tf32(yacc[nt], el, vh2);
                mma_tf32(yacc[nt], eh, vl2);
            }
        }
    }

    // ---- denominators -> smem, then scaled output ----
    #pragma unroll
    for (int g = 0; g < 4; g++) {
        float dsum = denl[g];
        #pragma unroll
        for (int off = 16; off; off >>= 1)
            dsum += __shfl_xor_sync(0xffffffffu, dsum, off);
        if (lane == 0) den_sh[w * 4 + g] = dsum;
    }
    __syncthreads();

    const float inv0 = 1.0f / den_sh[mbase + grp];
    const float inv1 = 1.0f / den_sh[mbase + grp + 8];
    #pragma unroll
    for (int nt = 0; nt < 2; nt++) {
        const int col = h * DHEAD + nbase + nt * 8 + 2 * qt;
        const int t0 = qbase + mbase + grp;
        *(float2*)&yout[(size_t)(b * T_SEQ + t0) * CDIM + col] =
            make_float2(yacc[nt][0] * inv0, yacc[nt][1] * inv0);
        *(float2*)&yout[(size_t)(b * T_SEQ + t0 + 8) * CDIM + col] =
            make_float2(yacc[nt][2] * inv1, yacc[nt][3] * inv1);
    }
}

// ---------------------------------------------------------------------------
extern "C" void kernel_launch(void* const* d_in, const int* in_sizes, int n_in,
                              void* d_out, int out_size)
{
    const float* x = nullptr; const float* Wa = nullptr; const float* Wp = nullptr;
    for (int i = 0; i < n_in; i++) {
        if (in_sizes[i] == BATCH * T_SEQ * CDIM)  x  = (const float*)d_in[i];
        else if (in_sizes[i] == C3 * CDIM)        Wa = (const float*)d_in[i];
        else if (in_sizes[i] == CDIM * CDIM)      Wp = (const float*)d_in[i];
    }
    float* out = (float*)d_out;

    void* qkv_p = nullptr; void* y_p = nullptr; void* vt_p = nullptr;
    cudaGetSymbolAddress(&qkv_p, g_qkv);
    cudaGetSymbolAddress(&y_p,   g_y);
    cudaGetSymbolAddress(&vt_p,  g_vt);
    float* qkv = (float*)qkv_p;
    float* y   = (float*)y_p;
    float* vtp = (float*)vt_p;

    const int GEMM_SMEM = 2 * GS_BUF * 4;     // 66,560 B
    const int ATTN_SMEM = A2_TOTAL * 4;       // 156,160 B -> 1 CTA/SM (16 warps)
    cudaFuncSetAttribute(gemm_tf32_kernel, cudaFuncAttributeMaxDynamicSharedMemorySize, GEMM_SMEM);
    cudaFuncSetAttribute(attn_kernel,      cudaFuncAttributeMaxDynamicSharedMemorySize, ATTN_SMEM);

    {   // qkv = x @ W_attn^T   (V columns redirected transposed into g_vt)
        dim3 grid(C3 / 128, MROWS / 128);
        gemm_tf32_kernel<<<grid, 256, GEMM_SMEM>>>(x, Wa, qkv, MROWS, C3, CDIM, vtp);
    }
    {   // penalized attention
        dim3 grid(T_SEQ / 64, HEADS, BATCH);
        attn_kernel<<<grid, 512, ATTN_SMEM>>>(qkv, vtp, y);
    }
    {   // out = y @ W_proj^T
        dim3 grid(CDIM / 128, MROWS / 128);
        gemm_tf32_kernel<<<grid, 256, GEMM_SMEM>>>(y, Wp, out, MROWS, CDIM, CDIM, nullptr);
    }
}